// round 1
// baseline (speedup 1.0000x reference)
#include <cuda_runtime.h>
#include <math.h>

#define NN   50000
#define EE   800000
#define GG   256
#define IND  32
#define HID  108
#define H2   54
#define H4   27
#define NCLS 10
#define NPB  64   // nodes per block for GEMM-ish kernels

// ---------------- scratch (device globals; no allocation allowed) ----------
__device__ float d_hA[NN * HID];
__device__ float d_hB[NN * HID];
__device__ float d_hp[NN * HID];
__device__ float d_agg[NN * HID];
__device__ float d_deg[NN];
__device__ float d_invdeg[NN];
__device__ float d_gsum[GG * HID];
__device__ float d_gcnt[GG];

// ---------------- utility ----------------
__global__ void k_zero(float* __restrict__ p, int n) {
    int i = blockIdx.x * blockDim.x + threadIdx.x;
    if (i < n) p[i] = 0.f;
}

__global__ void k_deg(const int* __restrict__ dst, float* __restrict__ deg) {
    int e = blockIdx.x * blockDim.x + threadIdx.x;
    if (e < EE) atomicAdd(&deg[dst[e]], 1.f);
}

__global__ void k_invdeg(const float* __restrict__ deg, float* __restrict__ invdeg) {
    int i = blockIdx.x * blockDim.x + threadIdx.x;
    if (i < NN) invdeg[i] = 1.f / fmaxf(deg[i], 1.f);
}

// ---------------- input embedding: h = x @ W_emb + b ----------------
__global__ void k_embed(const float* __restrict__ x, const float* __restrict__ W,
                        const float* __restrict__ b, float* __restrict__ hout) {
    __shared__ float sW[IND * HID];
    __shared__ float sx[IND];
    int t = threadIdx.x;  // 0..107
    for (int i = t; i < IND * HID; i += HID) sW[i] = W[i];
    float bias = b[t];
    __syncthreads();
    int n0 = blockIdx.x * NPB;
    int n1 = min(n0 + NPB, NN);
    for (int n = n0; n < n1; n++) {
        if (t < IND) sx[t] = x[n * IND + t];
        __syncthreads();
        float a0 = bias, a1 = 0.f, a2 = 0.f, a3 = 0.f;
#pragma unroll
        for (int k = 0; k < IND; k += 4) {
            a0 += sx[k + 0] * sW[(k + 0) * HID + t];
            a1 += sx[k + 1] * sW[(k + 1) * HID + t];
            a2 += sx[k + 2] * sW[(k + 2) * HID + t];
            a3 += sx[k + 3] * sW[(k + 3) * HID + t];
        }
        hout[n * HID + t] = (a0 + a1) + (a2 + a3);
        __syncthreads();
    }
}

// ---------------- pool: hp = relu(h @ W + b) ----------------
__global__ void k_pool(const float* __restrict__ h, const float* __restrict__ W,
                       const float* __restrict__ b, float* __restrict__ out) {
    __shared__ float sW[HID * HID];  // 46656 B
    __shared__ float sx[HID];
    int t = threadIdx.x;  // 0..107
    for (int i = t; i < HID * HID; i += HID) sW[i] = W[i];
    float bias = b[t];
    __syncthreads();
    int n0 = blockIdx.x * NPB;
    int n1 = min(n0 + NPB, NN);
    for (int n = n0; n < n1; n++) {
        sx[t] = h[n * HID + t];
        __syncthreads();
        float a0 = bias, a1 = 0.f, a2 = 0.f, a3 = 0.f;
#pragma unroll 9
        for (int k = 0; k < HID; k += 4) {
            a0 += sx[k + 0] * sW[(k + 0) * HID + t];
            a1 += sx[k + 1] * sW[(k + 1) * HID + t];
            a2 += sx[k + 2] * sW[(k + 2) * HID + t];
            a3 += sx[k + 3] * sW[(k + 3) * HID + t];
        }
        out[n * HID + t] = fmaxf((a0 + a1) + (a2 + a3), 0.f);
        __syncthreads();
    }
}

// ---------------- aggregation: agg[dst] += hp[src]  (warp per edge) --------
__global__ void k_agg(const float* __restrict__ hp, const int* __restrict__ src,
                      const int* __restrict__ dst, float* __restrict__ agg) {
    int g = blockIdx.x * blockDim.x + threadIdx.x;
    int e = g >> 5;
    int lane = g & 31;
    if (e >= EE) return;
    int s = src[e], d = dst[e];
    const float* ps = hp + (size_t)s * HID;
    float* pd = agg + (size_t)d * HID;
#pragma unroll
    for (int k = lane; k < HID; k += 32) atomicAdd(pd + k, __ldg(ps + k));
}

// ---------------- apply: h' = h + relu(l2norm(concat(h, agg*invdeg) @ W + b))
__global__ void k_apply(const float* __restrict__ h, const float* __restrict__ agg,
                        const float* __restrict__ invdeg,
                        const float* __restrict__ W, const float* __restrict__ b,
                        float* __restrict__ hout) {
    extern __shared__ float sW[];  // 2*HID*HID floats = 93312 B
    __shared__ float sx[2 * HID];
    __shared__ float red[4];
    __shared__ float snorm;
    int t = threadIdx.x;  // 0..127
    int wid = t >> 5, lane = t & 31;
    for (int i = t; i < 2 * HID * HID; i += 128) sW[i] = W[i];
    float bias = (t < HID) ? b[t] : 0.f;
    __syncthreads();
    int n0 = blockIdx.x * NPB;
    int n1 = min(n0 + NPB, NN);
    for (int n = n0; n < n1; n++) {
        float hv = 0.f;
        if (t < HID) {
            hv = h[n * HID + t];
            sx[t] = hv;
            sx[HID + t] = agg[n * HID + t] * invdeg[n];
        }
        __syncthreads();
        float acc = 0.f;
        if (t < HID) {
            float a0 = bias, a1 = 0.f, a2 = 0.f, a3 = 0.f;
#pragma unroll 6
            for (int k = 0; k < 2 * HID; k += 4) {
                a0 += sx[k + 0] * sW[(k + 0) * HID + t];
                a1 += sx[k + 1] * sW[(k + 1) * HID + t];
                a2 += sx[k + 2] * sW[(k + 2) * HID + t];
                a3 += sx[k + 3] * sW[(k + 3) * HID + t];
            }
            acc = (a0 + a1) + (a2 + a3);
        }
        float sq = acc * acc;
#pragma unroll
        for (int o = 16; o > 0; o >>= 1) sq += __shfl_down_sync(0xFFFFFFFFu, sq, o);
        if (lane == 0) red[wid] = sq;
        __syncthreads();
        if (t == 0) {
            float s = red[0] + red[1] + red[2] + red[3];
            snorm = 1.f / fmaxf(sqrtf(s), 1e-12f);
        }
        __syncthreads();
        if (t < HID) hout[n * HID + t] = hv + fmaxf(acc * snorm, 0.f);
        __syncthreads();
    }
}

// ---------------- readout sums: warp per node ----------------
__global__ void k_gsum(const float* __restrict__ h, const int* __restrict__ gid,
                       float* __restrict__ gsum, float* __restrict__ gcnt) {
    int g = blockIdx.x * blockDim.x + threadIdx.x;
    int n = g >> 5;
    int lane = g & 31;
    if (n >= NN) return;
    int gr = gid[n];
    const float* ph = h + (size_t)n * HID;
    float* pg = gsum + (size_t)gr * HID;
#pragma unroll
    for (int k = lane; k < HID; k += 32) atomicAdd(pg + k, ph[k]);
    if (lane == 0) atomicAdd(&gcnt[gr], 1.f);
}

// ---------------- MLP readout: one block per graph ----------------
__global__ void k_mlp(const float* __restrict__ gsum, const float* __restrict__ gcnt,
                      const float* __restrict__ W1, const float* __restrict__ b1,
                      const float* __restrict__ W2, const float* __restrict__ b2,
                      const float* __restrict__ W3, const float* __restrict__ b3,
                      float* __restrict__ out) {
    __shared__ float hg[HID];
    __shared__ float y1[H2];
    __shared__ float y2[H4];
    int g = blockIdx.x, t = threadIdx.x;  // 128 threads
    float ic = 1.f / fmaxf(gcnt[g], 1.f);
    if (t < HID) hg[t] = gsum[g * HID + t] * ic;
    __syncthreads();
    if (t < H2) {
        float a = b1[t];
#pragma unroll 4
        for (int k = 0; k < HID; k++) a += hg[k] * W1[k * H2 + t];
        y1[t] = fmaxf(a, 0.f);
    }
    __syncthreads();
    if (t < H4) {
        float a = b2[t];
#pragma unroll 6
        for (int k = 0; k < H2; k++) a += y1[k] * W2[k * H4 + t];
        y2[t] = fmaxf(a, 0.f);
    }
    __syncthreads();
    if (t < NCLS) {
        float a = b3[t];
#pragma unroll
        for (int k = 0; k < H4; k++) a += y2[k] * W3[k * NCLS + t];
        out[g * NCLS + t] = a;
    }
}

// ---------------- host launcher ----------------
extern "C" void kernel_launch(void* const* d_in, const int* in_sizes, int n_in,
                              void* d_out, int out_size) {
    const float* nodes_feat = (const float*)d_in[0];
    // d_in[1] edges_feat, d_in[2] nodes_num_norm_sqrt, d_in[3] edges_num_norm_sqrt: unused
    const int* src = (const int*)d_in[4];
    const int* dst = (const int*)d_in[5];
    const int* gid = (const int*)d_in[6];
    const float* W_emb = (const float*)d_in[7];
    const float* b_emb = (const float*)d_in[8];
    const float* W_pool = (const float*)d_in[9];
    const float* b_pool = (const float*)d_in[10];
    const float* W_app = (const float*)d_in[11];
    const float* b_app = (const float*)d_in[12];
    const float* W1 = (const float*)d_in[13];
    const float* b1 = (const float*)d_in[14];
    const float* W2 = (const float*)d_in[15];
    const float* b2 = (const float*)d_in[16];
    const float* W3 = (const float*)d_in[17];
    const float* b3 = (const float*)d_in[18];
    float* out = (float*)d_out;

    float *hA, *hB, *hp, *agg, *deg, *invdeg, *gsum, *gcnt;
    cudaGetSymbolAddress((void**)&hA, d_hA);
    cudaGetSymbolAddress((void**)&hB, d_hB);
    cudaGetSymbolAddress((void**)&hp, d_hp);
    cudaGetSymbolAddress((void**)&agg, d_agg);
    cudaGetSymbolAddress((void**)&deg, d_deg);
    cudaGetSymbolAddress((void**)&invdeg, d_invdeg);
    cudaGetSymbolAddress((void**)&gsum, d_gsum);
    cudaGetSymbolAddress((void**)&gcnt, d_gcnt);

    cudaFuncSetAttribute(k_apply, cudaFuncAttributeMaxDynamicSharedMemorySize,
                         2 * HID * HID * (int)sizeof(float));

    const int gemm_blocks = (NN + NPB - 1) / NPB;

    // degree
    k_zero<<<(NN + 255) / 256, 256>>>(deg, NN);
    k_deg<<<(EE + 255) / 256, 256>>>(dst, deg);
    k_invdeg<<<(NN + 255) / 256, 256>>>(deg, invdeg);

    // embedding
    k_embed<<<gemm_blocks, HID>>>(nodes_feat, W_emb, b_emb, hA);

    float* hc = hA;
    float* hn = hB;
    for (int l = 0; l < 4; l++) {
        k_zero<<<(NN * HID + 255) / 256, 256>>>(agg, NN * HID);
        k_pool<<<gemm_blocks, HID>>>(hc, W_pool + l * HID * HID, b_pool + l * HID, hp);
        k_agg<<<(EE * 32 + 255) / 256, 256>>>(hp, src, dst, agg);
        k_apply<<<gemm_blocks, 128, 2 * HID * HID * (int)sizeof(float)>>>(
            hc, agg, invdeg, W_app + l * 2 * HID * HID, b_app + l * HID, hn);
        float* tmp = hc; hc = hn; hn = tmp;
    }

    // readout
    k_zero<<<(GG * HID + 255) / 256, 256>>>(gsum, GG * HID);
    k_zero<<<(GG + 255) / 256, 256>>>(gcnt, GG);
    k_gsum<<<(NN * 32 + 255) / 256, 256>>>(hc, gid, gsum, gcnt);
    k_mlp<<<GG, 128>>>(gsum, gcnt, W1, b1, W2, b2, W3, b3, out);
}

// round 2
// speedup vs baseline: 1.8654x; 1.8654x over previous
#include <cuda_runtime.h>
#include <math.h>

#define NN   50000
#define EE   800000
#define GG   256
#define IND  32
#define HID  108
#define K2   216
#define KP2  220   // padded SMEM stride for apply W (bank-conflict free)
#define INDP 36    // padded SMEM stride for embed W
#define H2   54
#define H4   27
#define NCLS 10
#define BNP  64    // nodes per block in GEMM kernels
#define GRP  8     // node group (register tile)
#define NB   196   // scan blocks = ceil(NN/256)

// ---------------- scratch (device globals; no allocation allowed) ----------
__device__ float d_hA[NN * HID];
__device__ float d_hB[NN * HID];
__device__ float d_hp[NN * HID];
__device__ float d_agg[NN * HID];
__device__ int   d_cnt[NN];
__device__ int   d_bsum[256];
__device__ int   d_boff[256];
__device__ int   d_rowptr[NN + 1];
__device__ int   d_cursor[NN];
__device__ int   d_colsrc[EE];
__device__ float d_gsum[GG * HID];
__device__ float d_gcnt[GG];

// ---------------- utility ----------------
__global__ void k_zero(float* __restrict__ p, int n) {
    int i = blockIdx.x * blockDim.x + threadIdx.x;
    if (i < n) p[i] = 0.f;
}
__global__ void k_zero_int(int* __restrict__ p, int n) {
    int i = blockIdx.x * blockDim.x + threadIdx.x;
    if (i < n) p[i] = 0;
}

// ---------------- CSR build ----------------
__global__ void k_hist(const int* __restrict__ dst, int* __restrict__ cnt) {
    int e = blockIdx.x * blockDim.x + threadIdx.x;
    if (e < EE) atomicAdd(&cnt[dst[e]], 1);
}

__global__ void k_bsum(const int* __restrict__ cnt, int* __restrict__ bsum) {
    __shared__ int s[256];
    int i = blockIdx.x * 256 + threadIdx.x;
    s[threadIdx.x] = (i < NN) ? cnt[i] : 0;
    __syncthreads();
    for (int o = 128; o > 0; o >>= 1) {
        if (threadIdx.x < o) s[threadIdx.x] += s[threadIdx.x + o];
        __syncthreads();
    }
    if (threadIdx.x == 0) bsum[blockIdx.x] = s[0];
}

__global__ void k_scan_tops(const int* __restrict__ bsum, int* __restrict__ boff) {
    __shared__ int s[256];
    int t = threadIdx.x;
    int v = (t < NB) ? bsum[t] : 0;
    s[t] = v;
    __syncthreads();
    for (int o = 1; o < 256; o <<= 1) {
        int tv = (t >= o) ? s[t - o] : 0;
        __syncthreads();
        s[t] += tv;
        __syncthreads();
    }
    if (t < NB) boff[t] = s[t] - v;
}

__global__ void k_scan_block(const int* __restrict__ cnt, const int* __restrict__ boff,
                             int* __restrict__ rowptr, int* __restrict__ cursor) {
    __shared__ int s[256];
    int t = threadIdx.x;
    int i = blockIdx.x * 256 + t;
    int v = (i < NN) ? cnt[i] : 0;
    s[t] = v;
    __syncthreads();
    for (int o = 1; o < 256; o <<= 1) {
        int tv = (t >= o) ? s[t - o] : 0;
        __syncthreads();
        s[t] += tv;
        __syncthreads();
    }
    int excl = s[t] - v + boff[blockIdx.x];
    if (i < NN) { rowptr[i] = excl; cursor[i] = excl; }
    if (i == NN - 1) rowptr[NN] = excl + v;
}

__global__ void k_scatter(const int* __restrict__ src, const int* __restrict__ dst,
                          int* __restrict__ cursor, int* __restrict__ colsrc) {
    int e = blockIdx.x * blockDim.x + threadIdx.x;
    if (e < EE) {
        int pos = atomicAdd(&cursor[dst[e]], 1);
        colsrc[pos] = src[e];
    }
}

// ---------------- input embedding: h = x @ W_emb + b ----------------
__global__ void k_embed2(const float* __restrict__ x, const float* __restrict__ W,
                         const float* __restrict__ b, float* __restrict__ out) {
    __shared__ float sWT[HID * INDP];  // [col][k], padded stride
    __shared__ float sx[GRP * IND];
    int t = threadIdx.x;  // 128
    for (int i = t; i < IND * HID; i += 128) {
        int k = i / HID, c = i % HID;
        sWT[c * INDP + k] = W[i];
    }
    float bias = (t < HID) ? b[t] : 0.f;
    __syncthreads();
    int n0 = blockIdx.x * BNP;
    for (int g = 0; g < BNP / GRP; g++) {
        int nb = n0 + g * GRP;
        long base = (long)nb * IND;
        for (int i = t; i < GRP * IND; i += 128)
            sx[i] = (base + i < (long)NN * IND) ? x[base + i] : 0.f;
        __syncthreads();
        if (t < HID) {
            float acc[GRP];
#pragma unroll
            for (int n = 0; n < GRP; n++) acc[n] = bias;
#pragma unroll
            for (int k4 = 0; k4 < IND; k4 += 4) {
                float4 w = *(const float4*)&sWT[t * INDP + k4];
#pragma unroll
                for (int n = 0; n < GRP; n++) {
                    float4 xv = *(const float4*)&sx[n * IND + k4];
                    acc[n] += xv.x * w.x + xv.y * w.y + xv.z * w.z + xv.w * w.w;
                }
            }
#pragma unroll
            for (int n = 0; n < GRP; n++) {
                int node = nb + n;
                if (node < NN) out[(long)node * HID + t] = acc[n];
            }
        }
        __syncthreads();
    }
}

// ---------------- pool: hp = relu(h @ W + b) ----------------
__global__ void k_pool2(const float* __restrict__ h, const float* __restrict__ W,
                        const float* __restrict__ b, float* __restrict__ out) {
    extern __shared__ float sm[];
    float* sWT = sm;              // HID*HID, [col][k] (stride 108: conflict-free)
    float* sx = sm + HID * HID;   // GRP*HID
    int t = threadIdx.x;
    for (int i = t; i < HID * HID; i += 128) {
        int k = i / HID, c = i % HID;
        sWT[c * HID + k] = W[i];
    }
    float bias = (t < HID) ? b[t] : 0.f;
    __syncthreads();
    int n0 = blockIdx.x * BNP;
    for (int g = 0; g < BNP / GRP; g++) {
        int nb = n0 + g * GRP;
        long base = (long)nb * HID;
        for (int i = t; i < GRP * HID; i += 128)
            sx[i] = (base + i < (long)NN * HID) ? h[base + i] : 0.f;
        __syncthreads();
        if (t < HID) {
            float acc[GRP];
#pragma unroll
            for (int n = 0; n < GRP; n++) acc[n] = bias;
#pragma unroll 9
            for (int k4 = 0; k4 < HID; k4 += 4) {
                float4 w = *(const float4*)&sWT[t * HID + k4];
#pragma unroll
                for (int n = 0; n < GRP; n++) {
                    float4 xv = *(const float4*)&sx[n * HID + k4];
                    acc[n] += xv.x * w.x + xv.y * w.y + xv.z * w.z + xv.w * w.w;
                }
            }
#pragma unroll
            for (int n = 0; n < GRP; n++) {
                int node = nb + n;
                if (node < NN) out[(long)node * HID + t] = fmaxf(acc[n], 0.f);
            }
        }
        __syncthreads();
    }
}

// ---------------- aggregation via CSR: agg[d] = mean over hp[src] ----------
__global__ void k_agg3(const float* __restrict__ hp, const int* __restrict__ rowptr,
                       const int* __restrict__ colsrc, float* __restrict__ agg) {
    int w = (blockIdx.x * blockDim.x + threadIdx.x) >> 5;
    int lane = threadIdx.x & 31;
    if (w >= NN) return;
    int r0 = rowptr[w], r1 = rowptr[w + 1];
    float4 acc = make_float4(0.f, 0.f, 0.f, 0.f);
    const float4* hp4 = (const float4*)hp;
    for (int j0 = r0; j0 < r1; j0 += 32) {
        int myj = j0 + lane;
        int sreg = (myj < r1) ? colsrc[myj] : 0;
        int cnt = min(32, r1 - j0);
#pragma unroll 4
        for (int u = 0; u < cnt; u++) {
            int s = __shfl_sync(0xffffffffu, sreg, u);
            if (lane < 27) {
                float4 v = hp4[(long)s * 27 + lane];
                acc.x += v.x; acc.y += v.y; acc.z += v.z; acc.w += v.w;
            }
        }
    }
    float inv = 1.f / fmaxf((float)(r1 - r0), 1.f);
    if (lane < 27) {
        acc.x *= inv; acc.y *= inv; acc.z *= inv; acc.w *= inv;
        ((float4*)agg)[(long)w * 27 + lane] = acc;
    }
}

// ---- apply: h' = h + relu(l2norm(concat(h, agg) @ W + b)) ----
__global__ void k_apply2(const float* __restrict__ h, const float* __restrict__ agg,
                         const float* __restrict__ W, const float* __restrict__ b,
                         float* __restrict__ hout) {
    extern __shared__ float sm[];
    float* sWT = sm;                   // HID*KP2 (padded stride 220)
    float* sx = sWT + HID * KP2;       // GRP*K2
    float* sb = sx + GRP * K2;         // GRP*HID
    __shared__ float snorm[GRP];
    int t = threadIdx.x, lane = t & 31, wid = t >> 5;
    for (int i = t; i < K2 * HID; i += 128) {
        int k = i / HID, c = i % HID;
        sWT[c * KP2 + k] = W[i];
    }
    float bias = (t < HID) ? b[t] : 0.f;
    __syncthreads();
    int n0 = blockIdx.x * BNP;
    for (int g = 0; g < BNP / GRP; g++) {
        int nb = n0 + g * GRP;
        long base = (long)nb * HID;
        for (int i = t; i < GRP * HID; i += 128) {
            long gi = base + i;
            int n = i / HID, k = i % HID;
            float hv = (gi < (long)NN * HID) ? h[gi] : 0.f;
            float av = (gi < (long)NN * HID) ? agg[gi] : 0.f;
            sx[n * K2 + k] = hv;
            sx[n * K2 + HID + k] = av;
        }
        __syncthreads();
        float acc[GRP];
        if (t < HID) {
#pragma unroll
            for (int n = 0; n < GRP; n++) acc[n] = bias;
#pragma unroll 9
            for (int k4 = 0; k4 < K2; k4 += 4) {
                float4 w = *(const float4*)&sWT[t * KP2 + k4];
#pragma unroll
                for (int n = 0; n < GRP; n++) {
                    float4 xv = *(const float4*)&sx[n * K2 + k4];
                    acc[n] += xv.x * w.x + xv.y * w.y + xv.z * w.z + xv.w * w.w;
                }
            }
#pragma unroll
            for (int n = 0; n < GRP; n++) sb[n * HID + t] = acc[n] * acc[n];
        }
        __syncthreads();
        // 4 warps reduce 8 nodes (2 each)
#pragma unroll
        for (int rep = 0; rep < 2; rep++) {
            int n = wid + rep * 4;
            float s = 0.f;
            for (int c = lane; c < HID; c += 32) s += sb[n * HID + c];
#pragma unroll
            for (int o = 16; o > 0; o >>= 1) s += __shfl_down_sync(0xffffffffu, s, o);
            if (lane == 0) snorm[n] = 1.f / fmaxf(sqrtf(s), 1e-12f);
        }
        __syncthreads();
        if (t < HID) {
#pragma unroll
            for (int n = 0; n < GRP; n++) {
                int node = nb + n;
                if (node < NN)
                    hout[(long)node * HID + t] = sx[n * K2 + t] + fmaxf(acc[n] * snorm[n], 0.f);
            }
        }
        __syncthreads();
    }
}

// ---------------- readout sums: warp per node ----------------
__global__ void k_gsum(const float* __restrict__ h, const int* __restrict__ gid,
                       float* __restrict__ gsum, float* __restrict__ gcnt) {
    int g = blockIdx.x * blockDim.x + threadIdx.x;
    int n = g >> 5;
    int lane = g & 31;
    if (n >= NN) return;
    int gr = gid[n];
    const float* ph = h + (long)n * HID;
    float* pg = gsum + (long)gr * HID;
#pragma unroll
    for (int k = lane; k < HID; k += 32) atomicAdd(pg + k, ph[k]);
    if (lane == 0) atomicAdd(&gcnt[gr], 1.f);
}

// ---------------- MLP readout: one block per graph ----------------
__global__ void k_mlp(const float* __restrict__ gsum, const float* __restrict__ gcnt,
                      const float* __restrict__ W1, const float* __restrict__ b1,
                      const float* __restrict__ W2, const float* __restrict__ b2,
                      const float* __restrict__ W3, const float* __restrict__ b3,
                      float* __restrict__ out) {
    __shared__ float hg[HID];
    __shared__ float y1[H2];
    __shared__ float y2[H4];
    int g = blockIdx.x, t = threadIdx.x;  // 128 threads
    float ic = 1.f / fmaxf(gcnt[g], 1.f);
    if (t < HID) hg[t] = gsum[g * HID + t] * ic;
    __syncthreads();
    if (t < H2) {
        float a = b1[t];
#pragma unroll 4
        for (int k = 0; k < HID; k++) a += hg[k] * W1[k * H2 + t];
        y1[t] = fmaxf(a, 0.f);
    }
    __syncthreads();
    if (t < H4) {
        float a = b2[t];
#pragma unroll 6
        for (int k = 0; k < H2; k++) a += y1[k] * W2[k * H4 + t];
        y2[t] = fmaxf(a, 0.f);
    }
    __syncthreads();
    if (t < NCLS) {
        float a = b3[t];
#pragma unroll
        for (int k = 0; k < H4; k++) a += y2[k] * W3[k * NCLS + t];
        out[g * NCLS + t] = a;
    }
}

// ---------------- host launcher ----------------
extern "C" void kernel_launch(void* const* d_in, const int* in_sizes, int n_in,
                              void* d_out, int out_size) {
    const float* nodes_feat = (const float*)d_in[0];
    const int* src = (const int*)d_in[4];
    const int* dst = (const int*)d_in[5];
    const int* gid = (const int*)d_in[6];
    const float* W_emb = (const float*)d_in[7];
    const float* b_emb = (const float*)d_in[8];
    const float* W_pool = (const float*)d_in[9];
    const float* b_pool = (const float*)d_in[10];
    const float* W_app = (const float*)d_in[11];
    const float* b_app = (const float*)d_in[12];
    const float* W1 = (const float*)d_in[13];
    const float* b1 = (const float*)d_in[14];
    const float* W2 = (const float*)d_in[15];
    const float* b2 = (const float*)d_in[16];
    const float* W3 = (const float*)d_in[17];
    const float* b3 = (const float*)d_in[18];
    float* out = (float*)d_out;

    float *hA, *hB, *hp, *agg, *gsum, *gcnt;
    int *cnt, *bsum, *boff, *rowptr, *cursor, *colsrc;
    cudaGetSymbolAddress((void**)&hA, d_hA);
    cudaGetSymbolAddress((void**)&hB, d_hB);
    cudaGetSymbolAddress((void**)&hp, d_hp);
    cudaGetSymbolAddress((void**)&agg, d_agg);
    cudaGetSymbolAddress((void**)&cnt, d_cnt);
    cudaGetSymbolAddress((void**)&bsum, d_bsum);
    cudaGetSymbolAddress((void**)&boff, d_boff);
    cudaGetSymbolAddress((void**)&rowptr, d_rowptr);
    cudaGetSymbolAddress((void**)&cursor, d_cursor);
    cudaGetSymbolAddress((void**)&colsrc, d_colsrc);
    cudaGetSymbolAddress((void**)&gsum, d_gsum);
    cudaGetSymbolAddress((void**)&gcnt, d_gcnt);

    const int pool_smem = (HID * HID + GRP * HID) * (int)sizeof(float);
    const int apply_smem = (HID * KP2 + GRP * K2 + GRP * HID) * (int)sizeof(float);
    cudaFuncSetAttribute(k_pool2, cudaFuncAttributeMaxDynamicSharedMemorySize, pool_smem);
    cudaFuncSetAttribute(k_apply2, cudaFuncAttributeMaxDynamicSharedMemorySize, apply_smem);

    const int gemm_blocks = (NN + BNP - 1) / BNP;

    // ---- CSR build ----
    k_zero_int<<<(NN + 255) / 256, 256>>>(cnt, NN);
    k_hist<<<(EE + 255) / 256, 256>>>(dst, cnt);
    k_bsum<<<NB, 256>>>(cnt, bsum);
    k_scan_tops<<<1, 256>>>(bsum, boff);
    k_scan_block<<<NB, 256>>>(cnt, boff, rowptr, cursor);
    k_scatter<<<(EE + 255) / 256, 256>>>(src, dst, cursor, colsrc);

    // ---- embedding ----
    k_embed2<<<gemm_blocks, 128>>>(nodes_feat, W_emb, b_emb, hA);

    float* hc = hA;
    float* hn = hB;
    for (int l = 0; l < 4; l++) {
        k_pool2<<<gemm_blocks, 128, pool_smem>>>(hc, W_pool + l * HID * HID,
                                                 b_pool + l * HID, hp);
        k_agg3<<<(NN + 7) / 8, 256>>>(hp, rowptr, colsrc, agg);
        k_apply2<<<gemm_blocks, 128, apply_smem>>>(hc, agg, W_app + l * 2 * HID * HID,
                                                   b_app + l * HID, hn);
        float* tmp = hc; hc = hn; hn = tmp;
    }

    // ---- readout ----
    k_zero<<<(GG * HID + 255) / 256, 256>>>(gsum, GG * HID);
    k_zero<<<(GG + 255) / 256, 256>>>(gcnt, GG);
    k_gsum<<<(NN * 32 + 255) / 256, 256>>>(hc, gid, gsum, gcnt);
    k_mlp<<<GG, 128>>>(gsum, gcnt, W1, b1, W2, b2, W3, b3, out);
}

// round 3
// speedup vs baseline: 2.0353x; 1.0911x over previous
#include <cuda_runtime.h>
#include <math.h>
#include <stdint.h>

#define NN   50000
#define EE   800000
#define GG   256
#define IND  32
#define INDP 36    // padded SMEM stride for embed W (9 x 16B units, odd -> conflict-free)
#define HID  108
#define K2   216
#define KP2  220   // padded SMEM stride for apply W (55 x 16B units, odd -> conflict-free)
#define H2   54
#define H4   27
#define NCLS 10
#define BNP  64    // nodes per block in GEMM kernels
#define GRPP 16    // node group for pool/embed
#define GRPA 8     // node group for apply
#define NB   196   // scan blocks = ceil(NN/256)
#define GNB  64    // nodes per block for gsum

// packed fp32x2 FMA: both halves accumulate independently (exact IEEE per lane)
#define FMA2(acc, x, w) asm("fma.rn.f32x2 %0, %1, %2, %0;" : "+l"(acc) : "l"(x), "l"(w))

__device__ __forceinline__ float lo32(unsigned long long u) { return __uint_as_float((unsigned)u); }
__device__ __forceinline__ float hi32(unsigned long long u) { return __uint_as_float((unsigned)(u >> 32)); }

// ---------------- scratch (device globals; no allocation allowed) ----------
__device__ float d_hA[NN * HID];
__device__ float d_hB[NN * HID];
__device__ float d_hp[NN * HID];
__device__ float d_agg[NN * HID];
__device__ int   d_cnt[NN];
__device__ int   d_bsum[256];
__device__ int   d_boff[256];
__device__ int   d_rowptr[NN + 1];
__device__ int   d_cursor[NN];
__device__ int   d_colsrc[EE];
__device__ float d_gsum[GG * HID];
__device__ float d_gcnt[GG];

// ---------------- utility ----------------
__global__ void k_zero(float* __restrict__ p, int n) {
    int i = blockIdx.x * blockDim.x + threadIdx.x;
    if (i < n) p[i] = 0.f;
}
__global__ void k_zero_int(int* __restrict__ p, int n) {
    int i = blockIdx.x * blockDim.x + threadIdx.x;
    if (i < n) p[i] = 0;
}

// ---------------- CSR build ----------------
__global__ void k_hist(const int* __restrict__ dst, int* __restrict__ cnt) {
    int e = blockIdx.x * blockDim.x + threadIdx.x;
    if (e < EE) atomicAdd(&cnt[dst[e]], 1);
}

__global__ void k_bsum(const int* __restrict__ cnt, int* __restrict__ bsum) {
    __shared__ int s[256];
    int i = blockIdx.x * 256 + threadIdx.x;
    s[threadIdx.x] = (i < NN) ? cnt[i] : 0;
    __syncthreads();
    for (int o = 128; o > 0; o >>= 1) {
        if (threadIdx.x < o) s[threadIdx.x] += s[threadIdx.x + o];
        __syncthreads();
    }
    if (threadIdx.x == 0) bsum[blockIdx.x] = s[0];
}

__global__ void k_scan_tops(const int* __restrict__ bsum, int* __restrict__ boff) {
    __shared__ int s[256];
    int t = threadIdx.x;
    int v = (t < NB) ? bsum[t] : 0;
    s[t] = v;
    __syncthreads();
    for (int o = 1; o < 256; o <<= 1) {
        int tv = (t >= o) ? s[t - o] : 0;
        __syncthreads();
        s[t] += tv;
        __syncthreads();
    }
    if (t < NB) boff[t] = s[t] - v;
}

__global__ void k_scan_block(const int* __restrict__ cnt, const int* __restrict__ boff,
                             int* __restrict__ rowptr, int* __restrict__ cursor) {
    __shared__ int s[256];
    int t = threadIdx.x;
    int i = blockIdx.x * 256 + t;
    int v = (i < NN) ? cnt[i] : 0;
    s[t] = v;
    __syncthreads();
    for (int o = 1; o < 256; o <<= 1) {
        int tv = (t >= o) ? s[t - o] : 0;
        __syncthreads();
        s[t] += tv;
        __syncthreads();
    }
    int excl = s[t] - v + boff[blockIdx.x];
    if (i < NN) { rowptr[i] = excl; cursor[i] = excl; }
    if (i == NN - 1) rowptr[NN] = excl + v;
}

__global__ void k_scatter(const int* __restrict__ src, const int* __restrict__ dst,
                          int* __restrict__ cursor, int* __restrict__ colsrc) {
    int e = blockIdx.x * blockDim.x + threadIdx.x;
    if (e < EE) {
        int pos = atomicAdd(&cursor[dst[e]], 1);
        colsrc[pos] = src[e];
    }
}

// ---------------- input embedding: h = x @ W_emb + b (packed f32x2) --------
__global__ void k_embed3(const float* __restrict__ x, const float* __restrict__ W,
                         const float* __restrict__ b, float* __restrict__ out) {
    __shared__ float sWT[HID * INDP];  // [col][k], padded stride 36
    __shared__ float sx[GRPP * IND];   // [n][k]
    int t = threadIdx.x;  // 128
    for (int i = t; i < IND * HID; i += 128) {
        int k = i / HID, c = i % HID;
        sWT[c * INDP + k] = W[i];
    }
    float bias = (t < HID) ? b[t] : 0.f;
    __syncthreads();
    int n0 = blockIdx.x * BNP;
    for (int g = 0; g < BNP / GRPP; g++) {
        int nb = n0 + g * GRPP;
        long base = (long)nb * IND;
        for (int i = t; i < GRPP * IND; i += 128)
            sx[i] = (base + i < (long)NN * IND) ? x[base + i] : 0.f;
        __syncthreads();
        if (t < HID) {
            unsigned long long acc[GRPP];
#pragma unroll
            for (int n = 0; n < GRPP; n++) acc[n] = 0ull;
#pragma unroll
            for (int k4 = 0; k4 < IND; k4 += 4) {
                ulonglong2 w = *(const ulonglong2*)&sWT[t * INDP + k4];
#pragma unroll
                for (int n = 0; n < GRPP; n++) {
                    ulonglong2 xv = *(const ulonglong2*)&sx[n * IND + k4];
                    FMA2(acc[n], xv.x, w.x);
                    FMA2(acc[n], xv.y, w.y);
                }
            }
#pragma unroll
            for (int n = 0; n < GRPP; n++) {
                int node = nb + n;
                if (node < NN)
                    out[(long)node * HID + t] = lo32(acc[n]) + hi32(acc[n]) + bias;
            }
        }
        __syncthreads();
    }
}

// ---------------- pool: hp = relu(h @ W + b) (packed f32x2) ----------------
__global__ void k_pool3(const float* __restrict__ h, const float* __restrict__ W,
                        const float* __restrict__ b, float* __restrict__ out) {
    extern __shared__ float sm[];
    float* sWT = sm;              // [col][k], stride 108 (27x16B odd -> conflict-free)
    float* sx = sm + HID * HID;   // [n][k] GRPP*HID
    int t = threadIdx.x;
    for (int i = t; i < HID * HID; i += 128) {
        int k = i / HID, c = i % HID;
        sWT[c * HID + k] = W[i];
    }
    float bias = (t < HID) ? b[t] : 0.f;
    __syncthreads();
    int n0 = blockIdx.x * BNP;
    for (int g = 0; g < BNP / GRPP; g++) {
        int nb = n0 + g * GRPP;
        long base = (long)nb * HID;
        for (int i = t; i < GRPP * HID; i += 128)
            sx[i] = (base + i < (long)NN * HID) ? h[base + i] : 0.f;
        __syncthreads();
        if (t < HID) {
            unsigned long long acc[GRPP];
#pragma unroll
            for (int n = 0; n < GRPP; n++) acc[n] = 0ull;
#pragma unroll 9
            for (int k4 = 0; k4 < HID; k4 += 4) {
                ulonglong2 w = *(const ulonglong2*)&sWT[t * HID + k4];
#pragma unroll
                for (int n = 0; n < GRPP; n++) {
                    ulonglong2 xv = *(const ulonglong2*)&sx[n * HID + k4];
                    FMA2(acc[n], xv.x, w.x);
                    FMA2(acc[n], xv.y, w.y);
                }
            }
#pragma unroll
            for (int n = 0; n < GRPP; n++) {
                int node = nb + n;
                if (node < NN)
                    out[(long)node * HID + t] = fmaxf(lo32(acc[n]) + hi32(acc[n]) + bias, 0.f);
            }
        }
        __syncthreads();
    }
}

// ---------------- aggregation via CSR: agg[d] = mean over hp[src] ----------
__global__ void k_agg3(const float* __restrict__ hp, const int* __restrict__ rowptr,
                       const int* __restrict__ colsrc, float* __restrict__ agg) {
    int w = (blockIdx.x * blockDim.x + threadIdx.x) >> 5;
    int lane = threadIdx.x & 31;
    if (w >= NN) return;
    int r0 = rowptr[w], r1 = rowptr[w + 1];
    float4 acc = make_float4(0.f, 0.f, 0.f, 0.f);
    const float4* hp4 = (const float4*)hp;
    for (int j0 = r0; j0 < r1; j0 += 32) {
        int myj = j0 + lane;
        int sreg = (myj < r1) ? colsrc[myj] : 0;
        int cnt = min(32, r1 - j0);
#pragma unroll 4
        for (int u = 0; u < cnt; u++) {
            int s = __shfl_sync(0xffffffffu, sreg, u);
            if (lane < 27) {
                float4 v = hp4[(long)s * 27 + lane];
                acc.x += v.x; acc.y += v.y; acc.z += v.z; acc.w += v.w;
            }
        }
    }
    float inv = 1.f / fmaxf((float)(r1 - r0), 1.f);
    if (lane < 27) {
        acc.x *= inv; acc.y *= inv; acc.z *= inv; acc.w *= inv;
        ((float4*)agg)[(long)w * 27 + lane] = acc;
    }
}

// ---- apply: h' = h + relu(l2norm(concat(h, agg) @ W + b)) (packed f32x2) --
__global__ void k_apply3(const float* __restrict__ h, const float* __restrict__ agg,
                         const float* __restrict__ W, const float* __restrict__ b,
                         float* __restrict__ hout) {
    extern __shared__ float sm[];
    float* sWT = sm;                   // HID*KP2 (padded stride 220)
    float* sx = sWT + HID * KP2;       // GRPA*K2
    float* sb = sx + GRPA * K2;        // GRPA*HID (squares)
    __shared__ float snorm[GRPA];
    int t = threadIdx.x, lane = t & 31, wid = t >> 5;
    for (int i = t; i < K2 * HID; i += 128) {
        int k = i / HID, c = i % HID;
        sWT[c * KP2 + k] = W[i];
    }
    float bias = (t < HID) ? b[t] : 0.f;
    __syncthreads();
    int n0 = blockIdx.x * BNP;
    for (int g = 0; g < BNP / GRPA; g++) {
        int nb = n0 + g * GRPA;
        long base = (long)nb * HID;
        for (int i = t; i < GRPA * HID; i += 128) {
            long gi = base + i;
            int n = i / HID, k = i % HID;
            float hv = (gi < (long)NN * HID) ? h[gi] : 0.f;
            float av = (gi < (long)NN * HID) ? agg[gi] : 0.f;
            sx[n * K2 + k] = hv;
            sx[n * K2 + HID + k] = av;
        }
        __syncthreads();
        float accf[GRPA];
        if (t < HID) {
            unsigned long long acc[GRPA];
#pragma unroll
            for (int n = 0; n < GRPA; n++) acc[n] = 0ull;
#pragma unroll 6
            for (int k4 = 0; k4 < K2; k4 += 4) {
                ulonglong2 w = *(const ulonglong2*)&sWT[t * KP2 + k4];
#pragma unroll
                for (int n = 0; n < GRPA; n++) {
                    ulonglong2 xv = *(const ulonglong2*)&sx[n * K2 + k4];
                    FMA2(acc[n], xv.x, w.x);
                    FMA2(acc[n], xv.y, w.y);
                }
            }
#pragma unroll
            for (int n = 0; n < GRPA; n++) {
                accf[n] = lo32(acc[n]) + hi32(acc[n]) + bias;
                sb[n * HID + t] = accf[n] * accf[n];
            }
        }
        __syncthreads();
        // 4 warps reduce 8 nodes (2 each)
#pragma unroll
        for (int rep = 0; rep < 2; rep++) {
            int n = wid + rep * 4;
            float s = 0.f;
            for (int c = lane; c < HID; c += 32) s += sb[n * HID + c];
#pragma unroll
            for (int o = 16; o > 0; o >>= 1) s += __shfl_down_sync(0xffffffffu, s, o);
            if (lane == 0) snorm[n] = 1.f / fmaxf(sqrtf(s), 1e-12f);
        }
        __syncthreads();
        if (t < HID) {
#pragma unroll
            for (int n = 0; n < GRPA; n++) {
                int node = nb + n;
                if (node < NN)
                    hout[(long)node * HID + t] = sx[n * K2 + t] + fmaxf(accf[n] * snorm[n], 0.f);
            }
        }
        __syncthreads();
    }
}

// ---------------- readout sums: run-length accumulation (gids sorted) ------
__global__ void k_gsum2(const float* __restrict__ h, const int* __restrict__ gid,
                        float* __restrict__ gsum, float* __restrict__ gcnt) {
    int t = threadIdx.x;  // 128, only t<108 active
    if (t >= HID) return;
    int n0 = blockIdx.x * GNB;
    int n1 = min(n0 + GNB, NN);
    int gprev = __ldg(&gid[n0]);
    float accv = 0.f, cntv = 0.f;
    for (int n = n0; n < n1; n++) {
        int g = __ldg(&gid[n]);
        if (g != gprev) {
            atomicAdd(&gsum[(long)gprev * HID + t], accv);
            if (t == 0) atomicAdd(&gcnt[gprev], cntv);
            accv = 0.f; cntv = 0.f; gprev = g;
        }
        accv += h[(long)n * HID + t];
        cntv += 1.f;
    }
    atomicAdd(&gsum[(long)gprev * HID + t], accv);
    if (t == 0) atomicAdd(&gcnt[gprev], cntv);
}

// ---------------- MLP readout: one block per graph ----------------
__global__ void k_mlp(const float* __restrict__ gsum, const float* __restrict__ gcnt,
                      const float* __restrict__ W1, const float* __restrict__ b1,
                      const float* __restrict__ W2, const float* __restrict__ b2,
                      const float* __restrict__ W3, const float* __restrict__ b3,
                      float* __restrict__ out) {
    __shared__ float hg[HID];
    __shared__ float y1[H2];
    __shared__ float y2[H4];
    int g = blockIdx.x, t = threadIdx.x;  // 128 threads
    float ic = 1.f / fmaxf(gcnt[g], 1.f);
    if (t < HID) hg[t] = gsum[g * HID + t] * ic;
    __syncthreads();
    if (t < H2) {
        float a = b1[t];
#pragma unroll 4
        for (int k = 0; k < HID; k++) a += hg[k] * W1[k * H2 + t];
        y1[t] = fmaxf(a, 0.f);
    }
    __syncthreads();
    if (t < H4) {
        float a = b2[t];
#pragma unroll 6
        for (int k = 0; k < H2; k++) a += y1[k] * W2[k * H4 + t];
        y2[t] = fmaxf(a, 0.f);
    }
    __syncthreads();
    if (t < NCLS) {
        float a = b3[t];
#pragma unroll
        for (int k = 0; k < H4; k++) a += y2[k] * W3[k * NCLS + t];
        out[g * NCLS + t] = a;
    }
}

// ---------------- host launcher ----------------
extern "C" void kernel_launch(void* const* d_in, const int* in_sizes, int n_in,
                              void* d_out, int out_size) {
    const float* nodes_feat = (const float*)d_in[0];
    const int* src = (const int*)d_in[4];
    const int* dst = (const int*)d_in[5];
    const int* gid = (const int*)d_in[6];
    const float* W_emb = (const float*)d_in[7];
    const float* b_emb = (const float*)d_in[8];
    const float* W_pool = (const float*)d_in[9];
    const float* b_pool = (const float*)d_in[10];
    const float* W_app = (const float*)d_in[11];
    const float* b_app = (const float*)d_in[12];
    const float* W1 = (const float*)d_in[13];
    const float* b1 = (const float*)d_in[14];
    const float* W2 = (const float*)d_in[15];
    const float* b2 = (const float*)d_in[16];
    const float* W3 = (const float*)d_in[17];
    const float* b3 = (const float*)d_in[18];
    float* out = (float*)d_out;

    float *hA, *hB, *hp, *agg, *gsum, *gcnt;
    int *cnt, *bsum, *boff, *rowptr, *cursor, *colsrc;
    cudaGetSymbolAddress((void**)&hA, d_hA);
    cudaGetSymbolAddress((void**)&hB, d_hB);
    cudaGetSymbolAddress((void**)&hp, d_hp);
    cudaGetSymbolAddress((void**)&agg, d_agg);
    cudaGetSymbolAddress((void**)&cnt, d_cnt);
    cudaGetSymbolAddress((void**)&bsum, d_bsum);
    cudaGetSymbolAddress((void**)&boff, d_boff);
    cudaGetSymbolAddress((void**)&rowptr, d_rowptr);
    cudaGetSymbolAddress((void**)&cursor, d_cursor);
    cudaGetSymbolAddress((void**)&colsrc, d_colsrc);
    cudaGetSymbolAddress((void**)&gsum, d_gsum);
    cudaGetSymbolAddress((void**)&gcnt, d_gcnt);

    const int pool_smem = (HID * HID + GRPP * HID) * (int)sizeof(float);
    const int apply_smem = (HID * KP2 + GRPA * K2 + GRPA * HID) * (int)sizeof(float);
    cudaFuncSetAttribute(k_pool3, cudaFuncAttributeMaxDynamicSharedMemorySize, pool_smem);
    cudaFuncSetAttribute(k_apply3, cudaFuncAttributeMaxDynamicSharedMemorySize, apply_smem);

    const int gemm_blocks = (NN + BNP - 1) / BNP;

    // ---- CSR build ----
    k_zero_int<<<(NN + 255) / 256, 256>>>(cnt, NN);
    k_hist<<<(EE + 255) / 256, 256>>>(dst, cnt);
    k_bsum<<<NB, 256>>>(cnt, bsum);
    k_scan_tops<<<1, 256>>>(bsum, boff);
    k_scan_block<<<NB, 256>>>(cnt, boff, rowptr, cursor);
    k_scatter<<<(EE + 255) / 256, 256>>>(src, dst, cursor, colsrc);

    // ---- embedding ----
    k_embed3<<<gemm_blocks, 128>>>(nodes_feat, W_emb, b_emb, hA);

    float* hc = hA;
    float* hn = hB;
    for (int l = 0; l < 4; l++) {
        k_pool3<<<gemm_blocks, 128, pool_smem>>>(hc, W_pool + l * HID * HID,
                                                 b_pool + l * HID, hp);
        k_agg3<<<(NN + 7) / 8, 256>>>(hp, rowptr, colsrc, agg);
        k_apply3<<<gemm_blocks, 128, apply_smem>>>(hc, agg, W_app + l * 2 * HID * HID,
                                                   b_app + l * HID, hn);
        float* tmp = hc; hc = hn; hn = tmp;
    }

    // ---- readout ----
    k_zero<<<(GG * HID + 255) / 256, 256>>>(gsum, GG * HID);
    k_zero<<<(GG + 255) / 256, 256>>>(gcnt, GG);
    k_gsum2<<<(NN + GNB - 1) / GNB, 128>>>(hc, gid, gsum, gcnt);
    k_mlp<<<GG, 128>>>(gsum, gcnt, W1, b1, W2, b2, W3, b3, out);
}

// round 4
// speedup vs baseline: 3.6958x; 1.8158x over previous
#include <cuda_runtime.h>
#include <math.h>
#include <stdint.h>

#define NN   50000
#define EE   800000
#define GG   256
#define IND  32
#define HID  108
#define K2   216
#define H2   54
#define H4   27
#define NCLS 10
#define NB   196   // scan blocks = ceil(NN/256)
#define GNB  64    // nodes per block for gsum

// GEMM tiling
#define NT    64   // nodes per block
#define TPB   224  // threads: 28 col-groups x 8 node-groups
#define NCG   28   // col groups (4 cols each, covers 112 >= 108)
#define WSTR  112  // W smem row stride (floats)
#define NSTR  68   // x smem node stride (floats), 16B-aligned rows

// packed fp32x2 FMA: both halves accumulate independently (exact IEEE per lane)
#define FMA2(acc, x, w) asm("fma.rn.f32x2 %0, %1, %2, %0;" : "+l"(acc) : "l"(x), "l"(w))
#define PACKDUP(out, f) asm("mov.b64 %0, {%1, %1};" : "=l"(out) : "r"(__float_as_uint(f)))

__device__ __forceinline__ float lo32(unsigned long long u) { return __uint_as_float((unsigned)u); }
__device__ __forceinline__ float hi32(unsigned long long u) { return __uint_as_float((unsigned)(u >> 32)); }

// ---------------- scratch (device globals; no allocation allowed) ----------
__device__ float d_hA[NN * HID];
__device__ float d_hB[NN * HID];
__device__ float d_hp[NN * HID];
__device__ float d_agg[NN * HID];
__device__ int   d_cnt[NN];
__device__ int   d_bsum[256];
__device__ int   d_boff[256];
__device__ int   d_rowptr[NN + 1];
__device__ int   d_cursor[NN];
__device__ int   d_colsrc[EE];
__device__ float d_gsum[GG * HID];
__device__ float d_gcnt[GG];

// ---------------- utility ----------------
__global__ void k_zero(float* __restrict__ p, int n) {
    int i = blockIdx.x * blockDim.x + threadIdx.x;
    if (i < n) p[i] = 0.f;
}
__global__ void k_zero_int(int* __restrict__ p, int n) {
    int i = blockIdx.x * blockDim.x + threadIdx.x;
    if (i < n) p[i] = 0;
}

// ---------------- CSR build ----------------
__global__ void k_hist(const int* __restrict__ dst, int* __restrict__ cnt) {
    int e = blockIdx.x * blockDim.x + threadIdx.x;
    if (e < EE) atomicAdd(&cnt[dst[e]], 1);
}

__global__ void k_bsum(const int* __restrict__ cnt, int* __restrict__ bsum) {
    __shared__ int s[256];
    int i = blockIdx.x * 256 + threadIdx.x;
    s[threadIdx.x] = (i < NN) ? cnt[i] : 0;
    __syncthreads();
    for (int o = 128; o > 0; o >>= 1) {
        if (threadIdx.x < o) s[threadIdx.x] += s[threadIdx.x + o];
        __syncthreads();
    }
    if (threadIdx.x == 0) bsum[blockIdx.x] = s[0];
}

__global__ void k_scan_tops(const int* __restrict__ bsum, int* __restrict__ boff) {
    __shared__ int s[256];
    int t = threadIdx.x;
    int v = (t < NB) ? bsum[t] : 0;
    s[t] = v;
    __syncthreads();
    for (int o = 1; o < 256; o <<= 1) {
        int tv = (t >= o) ? s[t - o] : 0;
        __syncthreads();
        s[t] += tv;
        __syncthreads();
    }
    if (t < NB) boff[t] = s[t] - v;
}

__global__ void k_scan_block(const int* __restrict__ cnt, const int* __restrict__ boff,
                             int* __restrict__ rowptr, int* __restrict__ cursor) {
    __shared__ int s[256];
    int t = threadIdx.x;
    int i = blockIdx.x * 256 + t;
    int v = (i < NN) ? cnt[i] : 0;
    s[t] = v;
    __syncthreads();
    for (int o = 1; o < 256; o <<= 1) {
        int tv = (t >= o) ? s[t - o] : 0;
        __syncthreads();
        s[t] += tv;
        __syncthreads();
    }
    int excl = s[t] - v + boff[blockIdx.x];
    if (i < NN) { rowptr[i] = excl; cursor[i] = excl; }
    if (i == NN - 1) rowptr[NN] = excl + v;
}

__global__ void k_scatter(const int* __restrict__ src, const int* __restrict__ dst,
                          int* __restrict__ cursor, int* __restrict__ colsrc) {
    int e = blockIdx.x * blockDim.x + threadIdx.x;
    if (e < EE) {
        int pos = atomicAdd(&cursor[dst[e]], 1);
        colsrc[pos] = src[e];
    }
}

// ============ GEMM helpers (outer-product tiling) ============
// fill transposed x tile: xT[k][n] from M[node][kdim], kdim multiple of 4
__device__ __forceinline__ void fill_xT(float* xT, const float* __restrict__ M,
                                        int nb, int kdim, int t) {
    const float4* M4 = (const float4*)M;
    int q4 = kdim >> 2;
    for (int i = t; i < NT * q4; i += TPB) {
        int n = i / q4, q = i % q4;
        int node = nb + n;
        float4 v = make_float4(0.f, 0.f, 0.f, 0.f);
        if (node < NN) v = M4[(long)node * q4 + q];
        int kb = 4 * q;
        xT[(kb + 0) * NSTR + n] = v.x;
        xT[(kb + 1) * NSTR + n] = v.y;
        xT[(kb + 2) * NSTR + n] = v.z;
        xT[(kb + 3) * NSTR + n] = v.w;
    }
}

// fill W tile: sW[k][c] (stride WSTR, zero-pad cols 108..111) from W row-major [kdim][HID]
__device__ __forceinline__ void fill_W(float* sW, const float* __restrict__ W,
                                       int kdim, int t) {
    for (int i = t; i < kdim * HID; i += TPB) {
        int k = i / HID, c = i % HID;
        sW[k * WSTR + c] = W[i];
    }
    for (int i = t; i < kdim * 4; i += TPB) {
        int k = i >> 2;
        sW[k * WSTR + HID + (i & 3)] = 0.f;
    }
}

// inner accumulate over kdim rows
__device__ __forceinline__ void accum(const float* sW, const float* xT, int kdim,
                                      int cg, int n0, unsigned long long acc[4][4]) {
#pragma unroll 4
    for (int k = 0; k < kdim; k++) {
        float4 w = *(const float4*)&sW[k * WSTR + 4 * cg];
        ulonglong2 Xa = *(const ulonglong2*)&xT[k * NSTR + n0];
        ulonglong2 Xb = *(const ulonglong2*)&xT[k * NSTR + n0 + 4];
        unsigned long long w0, w1, w2, w3;
        PACKDUP(w0, w.x); PACKDUP(w1, w.y); PACKDUP(w2, w.z); PACKDUP(w3, w.w);
        FMA2(acc[0][0], Xa.x, w0); FMA2(acc[0][1], Xa.y, w0);
        FMA2(acc[0][2], Xb.x, w0); FMA2(acc[0][3], Xb.y, w0);
        FMA2(acc[1][0], Xa.x, w1); FMA2(acc[1][1], Xa.y, w1);
        FMA2(acc[1][2], Xb.x, w1); FMA2(acc[1][3], Xb.y, w1);
        FMA2(acc[2][0], Xa.x, w2); FMA2(acc[2][1], Xa.y, w2);
        FMA2(acc[2][2], Xb.x, w2); FMA2(acc[2][3], Xb.y, w2);
        FMA2(acc[3][0], Xa.x, w3); FMA2(acc[3][1], Xa.y, w3);
        FMA2(acc[3][2], Xb.x, w3); FMA2(acc[3][3], Xb.y, w3);
    }
}

// ---------------- input embedding: h = x @ W_emb + b ----------------
__global__ __launch_bounds__(TPB) void k_embed4(const float* __restrict__ x,
                                                const float* __restrict__ W,
                                                const float* __restrict__ b,
                                                float* __restrict__ out) {
    __shared__ float sW[IND * WSTR];
    __shared__ float xT[IND * NSTR];
    int t = threadIdx.x;
    int cg = t % NCG, ng = t / NCG;
    int n0 = 8 * ng;
    int nb = blockIdx.x * NT;
    fill_W(sW, W, IND, t);
    fill_xT(xT, x, nb, IND, t);
    __syncthreads();
    unsigned long long acc[4][4];
#pragma unroll
    for (int j = 0; j < 4; j++)
#pragma unroll
        for (int p = 0; p < 4; p++) acc[j][p] = 0ull;
    accum(sW, xT, IND, cg, n0, acc);
    if (cg < 27) {
        int c0 = 4 * cg;
        float4 bias = *(const float4*)&b[c0];
#pragma unroll
        for (int p = 0; p < 4; p++) {
            int na = nb + n0 + 2 * p, nc = na + 1;
            if (na < NN) {
                float4 v = make_float4(lo32(acc[0][p]) + bias.x, lo32(acc[1][p]) + bias.y,
                                       lo32(acc[2][p]) + bias.z, lo32(acc[3][p]) + bias.w);
                *(float4*)&out[(long)na * HID + c0] = v;
            }
            if (nc < NN) {
                float4 v = make_float4(hi32(acc[0][p]) + bias.x, hi32(acc[1][p]) + bias.y,
                                       hi32(acc[2][p]) + bias.z, hi32(acc[3][p]) + bias.w);
                *(float4*)&out[(long)nc * HID + c0] = v;
            }
        }
    }
}

// ---------------- pool: hp = relu(h @ W + b) ----------------
__global__ __launch_bounds__(TPB, 2) void k_pool4(const float* __restrict__ h,
                                                  const float* __restrict__ W,
                                                  const float* __restrict__ b,
                                                  float* __restrict__ out) {
    extern __shared__ float sm[];
    float* sW = sm;               // HID*WSTR
    float* xT = sm + HID * WSTR;  // HID*NSTR
    int t = threadIdx.x;
    int cg = t % NCG, ng = t / NCG;
    int n0 = 8 * ng;
    int nb = blockIdx.x * NT;
    fill_W(sW, W, HID, t);
    fill_xT(xT, h, nb, HID, t);
    __syncthreads();
    unsigned long long acc[4][4];
#pragma unroll
    for (int j = 0; j < 4; j++)
#pragma unroll
        for (int p = 0; p < 4; p++) acc[j][p] = 0ull;
    accum(sW, xT, HID, cg, n0, acc);
    if (cg < 27) {
        int c0 = 4 * cg;
        float4 bias = *(const float4*)&b[c0];
#pragma unroll
        for (int p = 0; p < 4; p++) {
            int na = nb + n0 + 2 * p, nc = na + 1;
            if (na < NN) {
                float4 v = make_float4(fmaxf(lo32(acc[0][p]) + bias.x, 0.f),
                                       fmaxf(lo32(acc[1][p]) + bias.y, 0.f),
                                       fmaxf(lo32(acc[2][p]) + bias.z, 0.f),
                                       fmaxf(lo32(acc[3][p]) + bias.w, 0.f));
                *(float4*)&out[(long)na * HID + c0] = v;
            }
            if (nc < NN) {
                float4 v = make_float4(fmaxf(hi32(acc[0][p]) + bias.x, 0.f),
                                       fmaxf(hi32(acc[1][p]) + bias.y, 0.f),
                                       fmaxf(hi32(acc[2][p]) + bias.z, 0.f),
                                       fmaxf(hi32(acc[3][p]) + bias.w, 0.f));
                *(float4*)&out[(long)nc * HID + c0] = v;
            }
        }
    }
}

// ---------------- aggregation via CSR: agg[d] = mean over hp[src] ----------
__global__ void k_agg3(const float* __restrict__ hp, const int* __restrict__ rowptr,
                       const int* __restrict__ colsrc, float* __restrict__ agg) {
    int w = (blockIdx.x * blockDim.x + threadIdx.x) >> 5;
    int lane = threadIdx.x & 31;
    if (w >= NN) return;
    int r0 = rowptr[w], r1 = rowptr[w + 1];
    float4 acc = make_float4(0.f, 0.f, 0.f, 0.f);
    const float4* hp4 = (const float4*)hp;
    for (int j0 = r0; j0 < r1; j0 += 32) {
        int myj = j0 + lane;
        int sreg = (myj < r1) ? colsrc[myj] : 0;
        int cnt = min(32, r1 - j0);
#pragma unroll 4
        for (int u = 0; u < cnt; u++) {
            int s = __shfl_sync(0xffffffffu, sreg, u);
            if (lane < 27) {
                float4 v = hp4[(long)s * 27 + lane];
                acc.x += v.x; acc.y += v.y; acc.z += v.z; acc.w += v.w;
            }
        }
    }
    float inv = 1.f / fmaxf((float)(r1 - r0), 1.f);
    if (lane < 27) {
        acc.x *= inv; acc.y *= inv; acc.z *= inv; acc.w *= inv;
        ((float4*)agg)[(long)w * 27 + lane] = acc;
    }
}

// ---- apply: h' = h + relu(l2norm(concat(h, agg) @ W + b)), 2-pass ----
__global__ __launch_bounds__(TPB, 2) void k_apply4(const float* __restrict__ h,
                                                   const float* __restrict__ agg,
                                                   const float* __restrict__ W,
                                                   const float* __restrict__ b,
                                                   float* __restrict__ hout) {
    extern __shared__ float sm[];
    float* sW = sm;                    // HID*WSTR
    float* xT = sW + HID * WSTR;       // HID*NSTR
    float* sp = xT + HID * NSTR;       // NT*NCG partial squares
    __shared__ float snorm[NT];
    int t = threadIdx.x;
    int cg = t % NCG, ng = t / NCG;
    int n0 = 8 * ng;
    int nb = blockIdx.x * NT;
    unsigned long long acc[4][4];
#pragma unroll
    for (int j = 0; j < 4; j++)
#pragma unroll
        for (int p = 0; p < 4; p++) acc[j][p] = 0ull;

    // pass 0: h part (W rows 0..107)
    fill_W(sW, W, HID, t);
    fill_xT(xT, h, nb, HID, t);
    __syncthreads();
    accum(sW, xT, HID, cg, n0, acc);
    __syncthreads();
    // pass 1: agg part (W rows 108..215)
    fill_W(sW, W + HID * HID, HID, t);
    fill_xT(xT, agg, nb, HID, t);
    __syncthreads();
    accum(sW, xT, HID, cg, n0, acc);

    // add bias, compute partial squares
    float4 bias = make_float4(0.f, 0.f, 0.f, 0.f);
    if (cg < 27) bias = *(const float4*)&b[4 * cg];
#pragma unroll
    for (int p = 0; p < 4; p++) {
        unsigned long long bd;
        float sqlo = 0.f, sqhi = 0.f;
        float bj[4] = {bias.x, bias.y, bias.z, bias.w};
#pragma unroll
        for (int j = 0; j < 4; j++) {
            float vlo = lo32(acc[j][p]) + bj[j];
            float vhi = hi32(acc[j][p]) + bj[j];
            // write back biased values
            asm("mov.b64 %0, {%1, %2};" : "=l"(bd) : "r"(__float_as_uint(vlo)), "r"(__float_as_uint(vhi)));
            acc[j][p] = bd;
            if (cg < 27) { sqlo += vlo * vlo; sqhi += vhi * vhi; }
        }
        sp[(n0 + 2 * p) * NCG + cg] = sqlo;
        sp[(n0 + 2 * p + 1) * NCG + cg] = sqhi;
    }
    __syncthreads();
    if (t < NT) {
        float s = 0.f;
#pragma unroll 7
        for (int c = 0; c < NCG; c++) s += sp[t * NCG + c];
        snorm[t] = 1.f / fmaxf(sqrtf(s), 1e-12f);
    }
    __syncthreads();

    if (cg < 27) {
        int c0 = 4 * cg;
        const float4* h4 = (const float4*)h;
#pragma unroll
        for (int p = 0; p < 4; p++) {
            int na = nb + n0 + 2 * p, nc = na + 1;
            float sa = snorm[n0 + 2 * p], sc = snorm[n0 + 2 * p + 1];
            if (na < NN) {
                float4 hv = h4[(long)na * 27 + cg];
                float4 v = make_float4(hv.x + fmaxf(lo32(acc[0][p]) * sa, 0.f),
                                       hv.y + fmaxf(lo32(acc[1][p]) * sa, 0.f),
                                       hv.z + fmaxf(lo32(acc[2][p]) * sa, 0.f),
                                       hv.w + fmaxf(lo32(acc[3][p]) * sa, 0.f));
                *(float4*)&hout[(long)na * HID + c0] = v;
            }
            if (nc < NN) {
                float4 hv = h4[(long)nc * 27 + cg];
                float4 v = make_float4(hv.x + fmaxf(hi32(acc[0][p]) * sc, 0.f),
                                       hv.y + fmaxf(hi32(acc[1][p]) * sc, 0.f),
                                       hv.z + fmaxf(hi32(acc[2][p]) * sc, 0.f),
                                       hv.w + fmaxf(hi32(acc[3][p]) * sc, 0.f));
                *(float4*)&hout[(long)nc * HID + c0] = v;
            }
        }
    }
}

// ---------------- readout sums: run-length accumulation (gids sorted) ------
__global__ void k_gsum2(const float* __restrict__ h, const int* __restrict__ gid,
                        float* __restrict__ gsum, float* __restrict__ gcnt) {
    int t = threadIdx.x;  // 128, only t<108 active
    if (t >= HID) return;
    int n0 = blockIdx.x * GNB;
    int n1 = min(n0 + GNB, NN);
    int gprev = __ldg(&gid[n0]);
    float accv = 0.f, cntv = 0.f;
    for (int n = n0; n < n1; n++) {
        int g = __ldg(&gid[n]);
        if (g != gprev) {
            atomicAdd(&gsum[(long)gprev * HID + t], accv);
            if (t == 0) atomicAdd(&gcnt[gprev], cntv);
            accv = 0.f; cntv = 0.f; gprev = g;
        }
        accv += h[(long)n * HID + t];
        cntv += 1.f;
    }
    atomicAdd(&gsum[(long)gprev * HID + t], accv);
    if (t == 0) atomicAdd(&gcnt[gprev], cntv);
}

// ---------------- MLP readout: one block per graph ----------------
__global__ void k_mlp(const float* __restrict__ gsum, const float* __restrict__ gcnt,
                      const float* __restrict__ W1, const float* __restrict__ b1,
                      const float* __restrict__ W2, const float* __restrict__ b2,
                      const float* __restrict__ W3, const float* __restrict__ b3,
                      float* __restrict__ out) {
    __shared__ float hg[HID];
    __shared__ float y1[H2];
    __shared__ float y2[H4];
    int g = blockIdx.x, t = threadIdx.x;  // 128 threads
    float ic = 1.f / fmaxf(gcnt[g], 1.f);
    if (t < HID) hg[t] = gsum[g * HID + t] * ic;
    __syncthreads();
    if (t < H2) {
        float a = b1[t];
#pragma unroll 4
        for (int k = 0; k < HID; k++) a += hg[k] * W1[k * H2 + t];
        y1[t] = fmaxf(a, 0.f);
    }
    __syncthreads();
    if (t < H4) {
        float a = b2[t];
#pragma unroll 6
        for (int k = 0; k < H2; k++) a += y1[k] * W2[k * H4 + t];
        y2[t] = fmaxf(a, 0.f);
    }
    __syncthreads();
    if (t < NCLS) {
        float a = b3[t];
#pragma unroll
        for (int k = 0; k < H4; k++) a += y2[k] * W3[k * NCLS + t];
        out[g * NCLS + t] = a;
    }
}

// ---------------- host launcher ----------------
extern "C" void kernel_launch(void* const* d_in, const int* in_sizes, int n_in,
                              void* d_out, int out_size) {
    const float* nodes_feat = (const float*)d_in[0];
    const int* src = (const int*)d_in[4];
    const int* dst = (const int*)d_in[5];
    const int* gid = (const int*)d_in[6];
    const float* W_emb = (const float*)d_in[7];
    const float* b_emb = (const float*)d_in[8];
    const float* W_pool = (const float*)d_in[9];
    const float* b_pool = (const float*)d_in[10];
    const float* W_app = (const float*)d_in[11];
    const float* b_app = (const float*)d_in[12];
    const float* W1 = (const float*)d_in[13];
    const float* b1 = (const float*)d_in[14];
    const float* W2 = (const float*)d_in[15];
    const float* b2 = (const float*)d_in[16];
    const float* W3 = (const float*)d_in[17];
    const float* b3 = (const float*)d_in[18];
    float* out = (float*)d_out;

    float *hA, *hB, *hp, *agg, *gsum, *gcnt;
    int *cnt, *bsum, *boff, *rowptr, *cursor, *colsrc;
    cudaGetSymbolAddress((void**)&hA, d_hA);
    cudaGetSymbolAddress((void**)&hB, d_hB);
    cudaGetSymbolAddress((void**)&hp, d_hp);
    cudaGetSymbolAddress((void**)&agg, d_agg);
    cudaGetSymbolAddress((void**)&cnt, d_cnt);
    cudaGetSymbolAddress((void**)&bsum, d_bsum);
    cudaGetSymbolAddress((void**)&boff, d_boff);
    cudaGetSymbolAddress((void**)&rowptr, d_rowptr);
    cudaGetSymbolAddress((void**)&cursor, d_cursor);
    cudaGetSymbolAddress((void**)&colsrc, d_colsrc);
    cudaGetSymbolAddress((void**)&gsum, d_gsum);
    cudaGetSymbolAddress((void**)&gcnt, d_gcnt);

    const int pool_smem = (HID * WSTR + HID * NSTR) * (int)sizeof(float);
    const int apply_smem = (HID * WSTR + HID * NSTR + NT * NCG) * (int)sizeof(float);
    cudaFuncSetAttribute(k_pool4, cudaFuncAttributeMaxDynamicSharedMemorySize, pool_smem);
    cudaFuncSetAttribute(k_apply4, cudaFuncAttributeMaxDynamicSharedMemorySize, apply_smem);

    const int gemm_blocks = (NN + NT - 1) / NT;

    // ---- CSR build ----
    k_zero_int<<<(NN + 255) / 256, 256>>>(cnt, NN);
    k_hist<<<(EE + 255) / 256, 256>>>(dst, cnt);
    k_bsum<<<NB, 256>>>(cnt, bsum);
    k_scan_tops<<<1, 256>>>(bsum, boff);
    k_scan_block<<<NB, 256>>>(cnt, boff, rowptr, cursor);
    k_scatter<<<(EE + 255) / 256, 256>>>(src, dst, cursor, colsrc);

    // ---- embedding ----
    k_embed4<<<gemm_blocks, TPB>>>(nodes_feat, W_emb, b_emb, hA);

    float* hc = hA;
    float* hn = hB;
    for (int l = 0; l < 4; l++) {
        k_pool4<<<gemm_blocks, TPB, pool_smem>>>(hc, W_pool + l * HID * HID,
                                                 b_pool + l * HID, hp);
        k_agg3<<<(NN + 7) / 8, 256>>>(hp, rowptr, colsrc, agg);
        k_apply4<<<gemm_blocks, TPB, apply_smem>>>(hc, agg, W_app + l * 2 * HID * HID,
                                                   b_app + l * HID, hn);
        float* tmp = hc; hc = hn; hn = tmp;
    }

    // ---- readout ----
    k_zero<<<(GG * HID + 255) / 256, 256>>>(gsum, GG * HID);
    k_zero<<<(GG + 255) / 256, 256>>>(gcnt, GG);
    k_gsum2<<<(NN + GNB - 1) / GNB, 128>>>(hc, gid, gsum, gcnt);
    k_mlp<<<GG, 128>>>(gsum, gcnt, W1, b1, W2, b2, W3, b3, out);
}

// round 6
// speedup vs baseline: 3.9152x; 1.0594x over previous
#include <cuda_runtime.h>
#include <math.h>
#include <stdint.h>

#define NN   50000
#define EE   800000
#define GG   256
#define IND  32
#define HID  108
#define H2   54
#define H4   27
#define NCLS 10
#define NB   196   // scan blocks = ceil(NN/256)
#define GNB  64    // nodes per block for gsum

// ---- mma GEMM tiling ----
#define SXS  120   // sX stride (floats)
#define SWS  116   // sW stride (floats)
#define KPAD 112   // padded K per pass (14 chunks of 8)

// ---- embed (FFMA2 path from R4) ----
#define NT    64
#define TPB   224
#define NCG   28
#define WSTR  112
#define NSTR  68
#define FMA2(acc, x, w) asm("fma.rn.f32x2 %0, %1, %2, %0;" : "+l"(acc) : "l"(x), "l"(w))
#define PACKDUP(out, f) asm("mov.b64 %0, {%1, %1};" : "=l"(out) : "r"(__float_as_uint(f)))
__device__ __forceinline__ float lo32(unsigned long long u) { return __uint_as_float((unsigned)u); }
__device__ __forceinline__ float hi32(unsigned long long u) { return __uint_as_float((unsigned)(u >> 32)); }

// ---------------- scratch ----------------
__device__ float d_hA[NN * HID];
__device__ float d_hB[NN * HID];
__device__ float d_hp[NN * HID];
__device__ float d_agg[NN * HID];
__device__ int   d_cnt[NN];
__device__ int   d_bsum[256];
__device__ int   d_boff[256];
__device__ int   d_rowptr[NN + 1];
__device__ int   d_cursor[NN];
__device__ int   d_colsrc[EE];
__device__ float d_gsum[GG * HID];
__device__ float d_gcnt[GG];

// ---------------- tf32 helpers ----------------
__device__ __forceinline__ void cvt_split(float x, uint32_t& hi, uint32_t& lo) {
    uint32_t h;
    asm("cvt.rna.tf32.f32 %0, %1;" : "=r"(h) : "f"(x));
    float r = x - __uint_as_float(h);
    uint32_t l;
    asm("cvt.rna.tf32.f32 %0, %1;" : "=r"(l) : "f"(r));
    hi = h; lo = l;
}

__device__ __forceinline__ void mma8(float acc[4], const uint32_t a[4], uint32_t b0, uint32_t b1) {
    asm volatile("mma.sync.aligned.m16n8k8.row.col.f32.tf32.tf32.f32 "
                 "{%0,%1,%2,%3}, {%4,%5,%6,%7}, {%8,%9}, {%0,%1,%2,%3};"
                 : "+f"(acc[0]), "+f"(acc[1]), "+f"(acc[2]), "+f"(acc[3])
                 : "r"(a[0]), "r"(a[1]), "r"(a[2]), "r"(a[3]), "r"(b0), "r"(b1));
}

// ---------------- utility ----------------
__global__ void k_zero(float* __restrict__ p, int n) {
    int i = blockIdx.x * blockDim.x + threadIdx.x;
    if (i < n) p[i] = 0.f;
}
__global__ void k_zero_int(int* __restrict__ p, int n) {
    int i = blockIdx.x * blockDim.x + threadIdx.x;
    if (i < n) p[i] = 0;
}

// ---------------- CSR build ----------------
__global__ void k_hist(const int* __restrict__ dst, int* __restrict__ cnt) {
    int e = blockIdx.x * blockDim.x + threadIdx.x;
    if (e < EE) atomicAdd(&cnt[dst[e]], 1);
}

__global__ void k_bsum(const int* __restrict__ cnt, int* __restrict__ bsum) {
    __shared__ int s[256];
    int i = blockIdx.x * 256 + threadIdx.x;
    s[threadIdx.x] = (i < NN) ? cnt[i] : 0;
    __syncthreads();
    for (int o = 128; o > 0; o >>= 1) {
        if (threadIdx.x < o) s[threadIdx.x] += s[threadIdx.x + o];
        __syncthreads();
    }
    if (threadIdx.x == 0) bsum[blockIdx.x] = s[0];
}

__global__ void k_scan_tops(const int* __restrict__ bsum, int* __restrict__ boff) {
    __shared__ int s[256];
    int t = threadIdx.x;
    int v = (t < NB) ? bsum[t] : 0;
    s[t] = v;
    __syncthreads();
    for (int o = 1; o < 256; o <<= 1) {
        int tv = (t >= o) ? s[t - o] : 0;
        __syncthreads();
        s[t] += tv;
        __syncthreads();
    }
    if (t < NB) boff[t] = s[t] - v;
}

__global__ void k_scan_block(const int* __restrict__ cnt, const int* __restrict__ boff,
                             int* __restrict__ rowptr, int* __restrict__ cursor) {
    __shared__ int s[256];
    int t = threadIdx.x;
    int i = blockIdx.x * 256 + t;
    int v = (i < NN) ? cnt[i] : 0;
    s[t] = v;
    __syncthreads();
    for (int o = 1; o < 256; o <<= 1) {
        int tv = (t >= o) ? s[t - o] : 0;
        __syncthreads();
        s[t] += tv;
        __syncthreads();
    }
    int excl = s[t] - v + boff[blockIdx.x];
    if (i < NN) { rowptr[i] = excl; cursor[i] = excl; }
    if (i == NN - 1) rowptr[NN] = excl + v;
}

__global__ void k_scatter(const int* __restrict__ src, const int* __restrict__ dst,
                          int* __restrict__ cursor, int* __restrict__ colsrc) {
    int e = blockIdx.x * blockDim.x + threadIdx.x;
    if (e < EE) {
        int pos = atomicAdd(&cursor[dst[e]], 1);
        colsrc[pos] = src[e];
    }
}

// ============ shared fill helpers for mma kernels ============
__device__ __forceinline__ void mfill_W(float* sW, const float* __restrict__ W, int t) {
    const float4* W4 = (const float4*)W;
    for (int i = t; i < 108 * 27; i += 256) {
        int k = i / 27, q = i % 27;
        *(float4*)&sW[k * SWS + 4 * q] = W4[i];
    }
    for (int i = t; i < KPAD * 2; i += 256) {
        int k = i >> 1, j = i & 1;
        *(float4*)&sW[k * SWS + 108 + 4 * j] = make_float4(0.f, 0.f, 0.f, 0.f);
    }
    for (int i = t; i < 4 * 27; i += 256) {
        int k = 108 + i / 27, q = i % 27;
        *(float4*)&sW[k * SWS + 4 * q] = make_float4(0.f, 0.f, 0.f, 0.f);
    }
}

__device__ __forceinline__ void mfill_X(float* sX, const float* __restrict__ M, int nb, int t) {
    const float4* M4 = (const float4*)M;
    for (int i = t; i < 64 * 27; i += 256) {
        int n = i / 27, q = i % 27;
        int node = nb + n;
        float4 v = make_float4(0.f, 0.f, 0.f, 0.f);
        if (node < NN) v = M4[(long)node * 27 + q];
        *(float4*)&sX[n * SXS + 4 * q] = v;
    }
    for (int i = t; i < 64 * 3; i += 256) {
        int n = i / 3, j = i % 3;
        *(float4*)&sX[n * SXS + 108 + 4 * j] = make_float4(0.f, 0.f, 0.f, 0.f);
    }
}

// one K-pass of mma accumulation: acc[7][4] over warp tile (16 nodes x 56 cols)
// PTX m16n8k8 row.col fragment mapping:
//   A: a0=(r=g,   k=tig) a1=(r=g+8, k=tig) a2=(r=g, k=tig+4) a3=(r=g+8, k=tig+4)
//   B: b0=(k=tig, c=g)   b1=(k=tig+4, c=g)
//   C: c0=(r=g, c=2tig) c1=(r=g, c=2tig+1) c2=(r=g+8, c=2tig) c3=(r=g+8, c=2tig+1)
__device__ __forceinline__ void mma_pass(const float* sX, const float* sW,
                                         int n16, int cbase0, int gid, int tig,
                                         float acc[7][4]) {
#pragma unroll 2
    for (int kc = 0; kc < KPAD; kc += 8) {
        uint32_t ah[4], al[4];
        cvt_split(sX[(n16 + gid) * SXS + kc + tig],           ah[0], al[0]);
        cvt_split(sX[(n16 + gid + 8) * SXS + kc + tig],       ah[1], al[1]);
        cvt_split(sX[(n16 + gid) * SXS + kc + tig + 4],       ah[2], al[2]);
        cvt_split(sX[(n16 + gid + 8) * SXS + kc + tig + 4],   ah[3], al[3]);
#pragma unroll
        for (int j = 0; j < 7; j++) {
            int c = cbase0 + 8 * j + gid;
            uint32_t bh0, bl0, bh1, bl1;
            cvt_split(sW[(kc + tig) * SWS + c],     bh0, bl0);
            cvt_split(sW[(kc + tig + 4) * SWS + c], bh1, bl1);
            mma8(acc[j], ah, bl0, bl1);   // hi*lo
            mma8(acc[j], al, bh0, bh1);   // lo*hi
            mma8(acc[j], ah, bh0, bh1);   // hi*hi
        }
    }
}

// ---------------- pool: hp = relu(h @ W + b), tf32 mma ----------------
__global__ __launch_bounds__(256, 2) void k_pool5(const float* __restrict__ h,
                                                  const float* __restrict__ W,
                                                  const float* __restrict__ b,
                                                  float* __restrict__ out) {
    extern __shared__ float sm[];
    float* sX = sm;               // 64*SXS
    float* sW = sm + 64 * SXS;    // KPAD*SWS
    __shared__ float sb[112];
    int t = threadIdx.x;
    int warp = t >> 5, lane = t & 31;
    int gid = lane >> 2, tig = lane & 3;
    int n16 = (warp & 3) * 16;
    int cbase0 = (warp >> 2) * 56;
    int nb = blockIdx.x * 64;

    mfill_W(sW, W, t);
    mfill_X(sX, h, nb, t);
    if (t < 112) sb[t] = (t < 108) ? b[t] : 0.f;
    __syncthreads();

    float acc[7][4];
#pragma unroll
    for (int j = 0; j < 7; j++)
#pragma unroll
        for (int p = 0; p < 4; p++) acc[j][p] = 0.f;

    mma_pass(sX, sW, n16, cbase0, gid, tig, acc);

    int node0 = nb + n16 + gid;
    int node1 = node0 + 8;
#pragma unroll
    for (int j = 0; j < 7; j++) {
        int c = cbase0 + 8 * j + 2 * tig;
        if (c < 108) {
            float bx = sb[c], by = sb[c + 1];
            if (node0 < NN) {
                float2 v = make_float2(fmaxf(acc[j][0] + bx, 0.f), fmaxf(acc[j][1] + by, 0.f));
                *(float2*)&out[(long)node0 * HID + c] = v;
            }
            if (node1 < NN) {
                float2 v = make_float2(fmaxf(acc[j][2] + bx, 0.f), fmaxf(acc[j][3] + by, 0.f));
                *(float2*)&out[(long)node1 * HID + c] = v;
            }
        }
    }
}

// ---- apply: h' = h + relu(l2norm(concat(h, agg) @ W + b)), tf32 mma, 2-pass ----
__global__ __launch_bounds__(256, 2) void k_apply5(const float* __restrict__ h,
                                                   const float* __restrict__ agg,
                                                   const float* __restrict__ W,
                                                   const float* __restrict__ b,
                                                   float* __restrict__ hout) {
    extern __shared__ float sm[];
    float* sX = sm;
    float* sW = sm + 64 * SXS;
    __shared__ float sb[112];
    __shared__ float sqsm[2][64];
    __shared__ float snorm[64];
    int t = threadIdx.x;
    int warp = t >> 5, lane = t & 31;
    int gid = lane >> 2, tig = lane & 3;
    int n16 = (warp & 3) * 16;
    int ch = warp >> 2;
    int cbase0 = ch * 56;
    int nb = blockIdx.x * 64;

    if (t < 112) sb[t] = (t < 108) ? b[t] : 0.f;

    float acc[7][4];
#pragma unroll
    for (int j = 0; j < 7; j++)
#pragma unroll
        for (int p = 0; p < 4; p++) acc[j][p] = 0.f;

    // pass 0: h x W[0:108], pass 1: agg x W[108:216]
    mfill_W(sW, W, t);
    mfill_X(sX, h, nb, t);
    __syncthreads();
    mma_pass(sX, sW, n16, cbase0, gid, tig, acc);
    __syncthreads();
    mfill_W(sW, W + HID * HID, t);
    mfill_X(sX, agg, nb, t);
    __syncthreads();
    mma_pass(sX, sW, n16, cbase0, gid, tig, acc);

    // bias + partial sum of squares per row
    float sq0 = 0.f, sq1 = 0.f;
#pragma unroll
    for (int j = 0; j < 7; j++) {
        int c = cbase0 + 8 * j + 2 * tig;
        if (c < 108) {
            float bx = sb[c], by = sb[c + 1];
            acc[j][0] += bx; acc[j][1] += by;
            acc[j][2] += bx; acc[j][3] += by;
            sq0 += acc[j][0] * acc[j][0] + acc[j][1] * acc[j][1];
            sq1 += acc[j][2] * acc[j][2] + acc[j][3] * acc[j][3];
        }
    }
    // reduce over tig lanes (same gid)
    sq0 += __shfl_xor_sync(0xffffffffu, sq0, 1);
    sq0 += __shfl_xor_sync(0xffffffffu, sq0, 2);
    sq1 += __shfl_xor_sync(0xffffffffu, sq1, 1);
    sq1 += __shfl_xor_sync(0xffffffffu, sq1, 2);
    if (tig == 0) {
        sqsm[ch][n16 + gid] = sq0;
        sqsm[ch][n16 + gid + 8] = sq1;
    }
    __syncthreads();
    if (t < 64) {
        float s = sqsm[0][t] + sqsm[1][t];
        snorm[t] = 1.f / fmaxf(sqrtf(s), 1e-12f);
    }
    __syncthreads();

    int node0 = nb + n16 + gid;
    int node1 = node0 + 8;
    float nrm0 = snorm[n16 + gid], nrm1 = snorm[n16 + gid + 8];
#pragma unroll
    for (int j = 0; j < 7; j++) {
        int c = cbase0 + 8 * j + 2 * tig;
        if (c < 108) {
            if (node0 < NN) {
                float2 hv = *(const float2*)&h[(long)node0 * HID + c];
                float2 v = make_float2(hv.x + fmaxf(acc[j][0] * nrm0, 0.f),
                                       hv.y + fmaxf(acc[j][1] * nrm0, 0.f));
                *(float2*)&hout[(long)node0 * HID + c] = v;
            }
            if (node1 < NN) {
                float2 hv = *(const float2*)&h[(long)node1 * HID + c];
                float2 v = make_float2(hv.x + fmaxf(acc[j][2] * nrm1, 0.f),
                                       hv.y + fmaxf(acc[j][3] * nrm1, 0.f));
                *(float2*)&hout[(long)node1 * HID + c] = v;
            }
        }
    }
}

// ============ embed (FFMA2 path, K=32) ============
__device__ __forceinline__ void fill_xT(float* xT, const float* __restrict__ M,
                                        int nb, int kdim, int t) {
    const float4* M4 = (const float4*)M;
    int q4 = kdim >> 2;
    for (int i = t; i < NT * q4; i += TPB) {
        int n = i / q4, q = i % q4;
        int node = nb + n;
        float4 v = make_float4(0.f, 0.f, 0.f, 0.f);
        if (node < NN) v = M4[(long)node * q4 + q];
        int kb = 4 * q;
        xT[(kb + 0) * NSTR + n] = v.x;
        xT[(kb + 1) * NSTR + n] = v.y;
        xT[(kb + 2) * NSTR + n] = v.z;
        xT[(kb + 3) * NSTR + n] = v.w;
    }
}

__device__ __forceinline__ void fill_W(float* sW, const float* __restrict__ W,
                                       int kdim, int t) {
    for (int i = t; i < kdim * HID; i += TPB) {
        int k = i / HID, c = i % HID;
        sW[k * WSTR + c] = W[i];
    }
    for (int i = t; i < kdim * 4; i += TPB) {
        int k = i >> 2;
        sW[k * WSTR + HID + (i & 3)] = 0.f;
    }
}

__device__ __forceinline__ void accum(const float* sW, const float* xT, int kdim,
                                      int cg, int n0, unsigned long long acc[4][4]) {
#pragma unroll 4
    for (int k = 0; k < kdim; k++) {
        float4 w = *(const float4*)&sW[k * WSTR + 4 * cg];
        ulonglong2 Xa = *(const ulonglong2*)&xT[k * NSTR + n0];
        ulonglong2 Xb = *(const ulonglong2*)&xT[k * NSTR + n0 + 4];
        unsigned long long w0, w1, w2, w3;
        PACKDUP(w0, w.x); PACKDUP(w1, w.y); PACKDUP(w2, w.z); PACKDUP(w3, w.w);
        FMA2(acc[0][0], Xa.x, w0); FMA2(acc[0][1], Xa.y, w0);
        FMA2(acc[0][2], Xb.x, w0); FMA2(acc[0][3], Xb.y, w0);
        FMA2(acc[1][0], Xa.x, w1); FMA2(acc[1][1], Xa.y, w1);
        FMA2(acc[1][2], Xb.x, w1); FMA2(acc[1][3], Xb.y, w1);
        FMA2(acc[2][0], Xa.x, w2); FMA2(acc[2][1], Xa.y, w2);
        FMA2(acc[2][2], Xb.x, w2); FMA2(acc[2][3], Xb.y, w2);
        FMA2(acc[3][0], Xa.x, w3); FMA2(acc[3][1], Xa.y, w3);
        FMA2(acc[3][2], Xb.x, w3); FMA2(acc[3][3], Xb.y, w3);
    }
}

__global__ __launch_bounds__(TPB) void k_embed4(const float* __restrict__ x,
                                                const float* __restrict__ W,
                                                const float* __restrict__ b,
                                                float* __restrict__ out) {
    __shared__ float sW[IND * WSTR];
    __shared__ float xT[IND * NSTR];
    int t = threadIdx.x;
    int cg = t % NCG, ng = t / NCG;
    int n0 = 8 * ng;
    int nb = blockIdx.x * NT;
    fill_W(sW, W, IND, t);
    fill_xT(xT, x, nb, IND, t);
    __syncthreads();
    unsigned long long acc[4][4];
#pragma unroll
    for (int j = 0; j < 4; j++)
#pragma unroll
        for (int p = 0; p < 4; p++) acc[j][p] = 0ull;
    accum(sW, xT, IND, cg, n0, acc);
    if (cg < 27) {
        int c0 = 4 * cg;
        float4 bias = *(const float4*)&b[c0];
#pragma unroll
        for (int p = 0; p < 4; p++) {
            int na = nb + n0 + 2 * p, nc = na + 1;
            if (na < NN) {
                float4 v = make_float4(lo32(acc[0][p]) + bias.x, lo32(acc[1][p]) + bias.y,
                                       lo32(acc[2][p]) + bias.z, lo32(acc[3][p]) + bias.w);
                *(float4*)&out[(long)na * HID + c0] = v;
            }
            if (nc < NN) {
                float4 v = make_float4(hi32(acc[0][p]) + bias.x, hi32(acc[1][p]) + bias.y,
                                       hi32(acc[2][p]) + bias.z, hi32(acc[3][p]) + bias.w);
                *(float4*)&out[(long)nc * HID + c0] = v;
            }
        }
    }
}

// ---------------- aggregation via CSR: agg[d] = mean over hp[src] ----------
__global__ void k_agg3(const float* __restrict__ hp, const int* __restrict__ rowptr,
                       const int* __restrict__ colsrc, float* __restrict__ agg) {
    int w = (blockIdx.x * blockDim.x + threadIdx.x) >> 5;
    int lane = threadIdx.x & 31;
    if (w >= NN) return;
    int r0 = rowptr[w], r1 = rowptr[w + 1];
    float4 acc = make_float4(0.f, 0.f, 0.f, 0.f);
    const float4* hp4 = (const float4*)hp;
    for (int j0 = r0; j0 < r1; j0 += 32) {
        int myj = j0 + lane;
        int sreg = (myj < r1) ? colsrc[myj] : 0;
        int cnt = min(32, r1 - j0);
#pragma unroll 4
        for (int u = 0; u < cnt; u++) {
            int s = __shfl_sync(0xffffffffu, sreg, u);
            if (lane < 27) {
                float4 v = hp4[(long)s * 27 + lane];
                acc.x += v.x; acc.y += v.y; acc.z += v.z; acc.w += v.w;
            }
        }
    }
    float inv = 1.f / fmaxf((float)(r1 - r0), 1.f);
    if (lane < 27) {
        acc.x *= inv; acc.y *= inv; acc.z *= inv; acc.w *= inv;
        ((float4*)agg)[(long)w * 27 + lane] = acc;
    }
}

// ---------------- readout sums: run-length accumulation (gids sorted) ------
__global__ void k_gsum2(const float* __restrict__ h, const int* __restrict__ gid,
                        float* __restrict__ gsum, float* __restrict__ gcnt) {
    int t = threadIdx.x;
    if (t >= HID) return;
    int n0 = blockIdx.x * GNB;
    int n1 = min(n0 + GNB, NN);
    int gprev = __ldg(&gid[n0]);
    float accv = 0.f, cntv = 0.f;
    for (int n = n0; n < n1; n++) {
        int g = __ldg(&gid[n]);
        if (g != gprev) {
            atomicAdd(&gsum[(long)gprev * HID + t], accv);
            if (t == 0) atomicAdd(&gcnt[gprev], cntv);
            accv = 0.f; cntv = 0.f; gprev = g;
        }
        accv += h[(long)n * HID + t];
        cntv += 1.f;
    }
    atomicAdd(&gsum[(long)gprev * HID + t], accv);
    if (t == 0) atomicAdd(&gcnt[gprev], cntv);
}

// ---------------- MLP readout ----------------
__global__ void k_mlp(const float* __restrict__ gsum, const float* __restrict__ gcnt,
                      const float* __restrict__ W1, const float* __restrict__ b1,
                      const float* __restrict__ W2, const float* __restrict__ b2,
                      const float* __restrict__ W3, const float* __restrict__ b3,
                      float* __restrict__ out) {
    __shared__ float hg[HID];
    __shared__ float y1[H2];
    __shared__ float y2[H4];
    int g = blockIdx.x, t = threadIdx.x;
    float ic = 1.f / fmaxf(gcnt[g], 1.f);
    if (t < HID) hg[t] = gsum[g * HID + t] * ic;
    __syncthreads();
    if (t < H2) {
        float a = b1[t];
#pragma unroll 4
        for (int k = 0; k < HID; k++) a += hg[k] * W1[k * H2 + t];
        y1[t] = fmaxf(a, 0.f);
    }
    __syncthreads();
    if (t < H4) {
        float a = b2[t];
#pragma unroll 6
        for (int k = 0; k < H2; k++) a += y1[k] * W2[k * H4 + t];
        y2[t] = fmaxf(a, 0.f);
    }
    __syncthreads();
    if (t < NCLS) {
        float a = b3[t];
#pragma unroll
        for (int k = 0; k < H4; k++) a += y2[k] * W3[k * NCLS + t];
        out[g * NCLS + t] = a;
    }
}

// ---------------- host launcher ----------------
extern "C" void kernel_launch(void* const* d_in, const int* in_sizes, int n_in,
                              void* d_out, int out_size) {
    const float* nodes_feat = (const float*)d_in[0];
    const int* src = (const int*)d_in[4];
    const int* dst = (const int*)d_in[5];
    const int* gid = (const int*)d_in[6];
    const float* W_emb = (const float*)d_in[7];
    const float* b_emb = (const float*)d_in[8];
    const float* W_pool = (const float*)d_in[9];
    const float* b_pool = (const float*)d_in[10];
    const float* W_app = (const float*)d_in[11];
    const float* b_app = (const float*)d_in[12];
    const float* W1 = (const float*)d_in[13];
    const float* b1 = (const float*)d_in[14];
    const float* W2 = (const float*)d_in[15];
    const float* b2 = (const float*)d_in[16];
    const float* W3 = (const float*)d_in[17];
    const float* b3 = (const float*)d_in[18];
    float* out = (float*)d_out;

    float *hA, *hB, *hp, *agg, *gsum, *gcnt;
    int *cnt, *bsum, *boff, *rowptr, *cursor, *colsrc;
    cudaGetSymbolAddress((void**)&hA, d_hA);
    cudaGetSymbolAddress((void**)&hB, d_hB);
    cudaGetSymbolAddress((void**)&hp, d_hp);
    cudaGetSymbolAddress((void**)&agg, d_agg);
    cudaGetSymbolAddress((void**)&cnt, d_cnt);
    cudaGetSymbolAddress((void**)&bsum, d_bsum);
    cudaGetSymbolAddress((void**)&boff, d_boff);
    cudaGetSymbolAddress((void**)&rowptr, d_rowptr);
    cudaGetSymbolAddress((void**)&cursor, d_cursor);
    cudaGetSymbolAddress((void**)&colsrc, d_colsrc);
    cudaGetSymbolAddress((void**)&gsum, d_gsum);
    cudaGetSymbolAddress((void**)&gcnt, d_gcnt);

    const int mma_smem = (64 * SXS + KPAD * SWS) * (int)sizeof(float);
    cudaFuncSetAttribute(k_pool5, cudaFuncAttributeMaxDynamicSharedMemorySize, mma_smem);
    cudaFuncSetAttribute(k_apply5, cudaFuncAttributeMaxDynamicSharedMemorySize, mma_smem);

    const int gemm_blocks = (NN + 63) / 64;

    // order arranged so ncu (-s 5 -c 1) captures k_pool5 (6th launch)
    k_embed4<<<gemm_blocks, TPB>>>(nodes_feat, W_emb, b_emb, hA);             // 1
    k_zero_int<<<(NN + 255) / 256, 256>>>(cnt, NN);                           // 2
    k_hist<<<(EE + 255) / 256, 256>>>(dst, cnt);                              // 3
    k_bsum<<<NB, 256>>>(cnt, bsum);                                           // 4
    k_scan_tops<<<1, 256>>>(bsum, boff);                                      // 5
    k_pool5<<<gemm_blocks, 256, mma_smem>>>(hA, W_pool, b_pool, hp);          // 6 <- profiled
    k_scan_block<<<NB, 256>>>(cnt, boff, rowptr, cursor);                     // 7
    k_scatter<<<(EE + 255) / 256, 256>>>(src, dst, cursor, colsrc);           // 8

    float* hc = hA;
    float* hn = hB;
    for (int l = 0; l < 4; l++) {
        if (l > 0)
            k_pool5<<<gemm_blocks, 256, mma_smem>>>(hc, W_pool + l * HID * HID,
                                                    b_pool + l * HID, hp);
        k_agg3<<<(NN + 7) / 8, 256>>>(hp, rowptr, colsrc, agg);
        k_apply5<<<gemm_blocks, 256, mma_smem>>>(hc, agg, W_app + l * 2 * HID * HID,
                                                 b_app + l * HID, hn);
        float* tmp = hc; hc = hn; hn = tmp;
    }

    // readout
    k_zero<<<(GG * HID + 255) / 256, 256>>>(gsum, GG * HID);
    k_zero<<<(GG + 255) / 256, 256>>>(gcnt, GG);
    k_gsum2<<<(NN + GNB - 1) / GNB, 128>>>(hc, gid, gsum, gcnt);
    k_mlp<<<GG, 128>>>(gsum, gcnt, W1, b1, W2, b2, W3, b3, out);
}